// round 13
// baseline (speedup 1.0000x reference)
#include <cuda_runtime.h>
#include <cub/cub.cuh>

// Problem constants (fixed by the reference setup_inputs)
constexpr int B  = 64;
constexpr int H  = 512;
constexpr int W  = 512;
constexpr int HW = H * W;        // 262144 = 2^18
constexpr int N  = B * HW;       // 16777216

// Group sort: 16 groups x 4 batches. Key packs (local batch, 30-bit score):
// score keys have bits 30..31 constant '01' (scores in [0,1)), so 2 bits are
// free. Sorted position within a group == final output row (each batch has
// exactly HW elements).
constexpr int G   = 16;
constexpr int BPG = 4;             // batches per group
constexpr int M   = N / G;         // 1048576 elements per group
constexpr size_t TEMP_PER = 8u << 20;

// 4 created streams (memory-check proven) + the capture stream = 5 lanes.
constexpr int S = 4;
constexpr int LANES = S + 1;

// Static scratch (no allocation allowed)
__device__ unsigned g_keys_a[N];
__device__ unsigned g_keys_b[N];
__device__ unsigned g_vals_a[N];
__device__ unsigned g_vals_b[N];
__device__ float2   g_pairs[N];
__device__ unsigned char g_temp[G * TEMP_PER];

// ---------------------------------------------------------------------------
// Kernel 1 (per group): 8-neighbor NMS + packed key encode + offset pairs.
//   key  = (local_batch << 30) | (descending-score bits [0,30))
//   val  = idx within image (18 bits)
// Stable ascending sort of one group == final order for its 4 batches.
// ---------------------------------------------------------------------------
__global__ void nms_encode_kernel(const float* __restrict__ hm,
                                  const float* __restrict__ off,
                                  unsigned* __restrict__ keys,
                                  unsigned* __restrict__ vals,
                                  float2* __restrict__ pairs,
                                  int group) {
    int e = blockIdx.x * blockDim.x + threadIdx.x;
    if (e >= M) return;
    int g   = group * M + e;
    int idx = g & (HW - 1);
    int b   = g >> 18;
    int y   = idx >> 9;
    int x   = idx & (W - 1);

    const float* img = hm + (size_t)b * HW;
    float v = __ldg(img + idx);

    float m = -__int_as_float(0x7f800000);  // -inf
    if (y > 0) {
        const float* r = img + (y - 1) * W + x;
        if (x > 0)      m = fmaxf(m, __ldg(r - 1));
        m = fmaxf(m, __ldg(r));
        if (x < W - 1)  m = fmaxf(m, __ldg(r + 1));
    }
    {
        const float* r = img + y * W + x;
        if (x > 0)      m = fmaxf(m, __ldg(r - 1));
        if (x < W - 1)  m = fmaxf(m, __ldg(r + 1));
    }
    if (y < H - 1) {
        const float* r = img + (y + 1) * W + x;
        if (x > 0)      m = fmaxf(m, __ldg(r - 1));
        m = fmaxf(m, __ldg(r));
        if (x < W - 1)  m = fmaxf(m, __ldg(r + 1));
    }

    float jv = (m >= v) ? 0.6f * v : v;

    // float -> descending-ordered bits; bits 30..31 of d are constant '01'
    unsigned u = __float_as_uint(jv);
    unsigned e32 = u ^ 0x80000000u;      // jv >= 0 always
    unsigned d   = ~e32;
    keys[g] = ((unsigned)(b & (BPG - 1)) << 30) | (d & 0x3FFFFFFFu);
    vals[g] = (unsigned)idx;

    const float* ob = off + (size_t)b * 2 * HW;
    float xo = __ldg(ob + idx);        // channel 0: x-offset
    float yo = __ldg(ob + HW + idx);   // channel 1: y-offset
    pairs[g] = make_float2(xo, yo);
}

// ---------------------------------------------------------------------------
// Kernel 2 (per group): direct decode on the group's lane.
// Sorted position p (global) is the final output row; batch = p >> 18.
// Coalesced key/val reads, L2-resident pair gathers, float4 writes.
// ---------------------------------------------------------------------------
__global__ void decode_kernel(const unsigned* __restrict__ ks,
                              const unsigned* __restrict__ vs,
                              const float2* __restrict__ pairs,
                              float* __restrict__ out,
                              int group) {
    int q = blockIdx.x * blockDim.x + threadIdx.x;   // quad index in group
    if (q >= M / 4) return;
    size_t p0 = (size_t)group * M + (size_t)q * 4;   // global output row
    size_t q0 = ((size_t)group * M) / 4 + (size_t)q; // global quad index

    uint4 kq = ((const uint4*)ks)[q0];
    uint4 vq = ((const uint4*)vs)[q0];
    unsigned kk[4] = {kq.x, kq.y, kq.z, kq.w};
    unsigned vv[4] = {vq.x, vq.y, vq.z, vq.w};

    float r[12];
#pragma unroll
    for (int i = 0; i < 4; i++) {
        size_t p = p0 + i;
        unsigned b   = (unsigned)(p >> 18);
        unsigned idx = vv[i];
        unsigned d   = (kk[i] & 0x3FFFFFFFu) | 0x40000000u;  // restore '01'
        unsigned u   = (~d) ^ 0x80000000u;
        float score  = __uint_as_float(u);
        int y = (int)(idx >> 9), x = (int)(idx & (W - 1));

        float2 pr = __ldg(&pairs[((size_t)b << 18) | idx]);
        r[3 * i + 0] = (float)y + pr.y + 0.5f;   // y-offset
        r[3 * i + 1] = (float)x + pr.x + 0.5f;   // x-offset
        r[3 * i + 2] = score;
    }

    float4* o4 = (float4*)(out + p0 * 3);
    o4[0] = make_float4(r[0], r[1], r[2], r[3]);
    o4[1] = make_float4(r[4], r[5], r[6], r[7]);
    o4[2] = make_float4(r[8], r[9], r[10], r[11]);
}

extern "C" void kernel_launch(void* const* d_in, const int* in_sizes, int n_in,
                              void* d_out, int out_size) {
    const float* hm  = (const float*)d_in[0];
    const float* off = (const float*)d_in[1];
    float* out = (float*)d_out;

    unsigned *ka, *kb, *va, *vb;
    float2* pr;
    unsigned char* tmp;
    cudaGetSymbolAddress((void**)&ka, g_keys_a);
    cudaGetSymbolAddress((void**)&kb, g_keys_b);
    cudaGetSymbolAddress((void**)&va, g_vals_a);
    cudaGetSymbolAddress((void**)&vb, g_vals_b);
    cudaGetSymbolAddress((void**)&pr, g_pairs);
    cudaGetSymbolAddress((void**)&tmp, g_temp);

    // 4 created streams (proven clean) + stream 0 as a free 5th lane.
    // Created/destroyed within this call; graph replay never re-runs host code.
    cudaStream_t streams[S];
    cudaEvent_t ev_fork, ev_join[S];
    for (int s = 0; s < S; s++)
        cudaStreamCreateWithFlags(&streams[s], cudaStreamNonBlocking);
    cudaEventCreateWithFlags(&ev_fork, cudaEventDisableTiming);
    for (int s = 0; s < S; s++)
        cudaEventCreateWithFlags(&ev_join[s], cudaEventDisableTiming);

    cudaEventRecord(ev_fork, 0);
    for (int s = 0; s < S; s++)
        cudaStreamWaitEvent(streams[s], ev_fork, 0);

    const int gblocks = (M + 255) / 256;
    const int dblocks = (M / 4 + 255) / 256;
    for (int g = 0; g < G; g++) {
        int lane = g % LANES;
        cudaStream_t st = (lane == 0) ? (cudaStream_t)0 : streams[lane - 1];

        // This group's chain starts as soon as its slice is encoded,
        // overlapping other lanes' encode/sort/decode work.
        nms_encode_kernel<<<gblocks, 256, 0, st>>>(hm, off, ka, va, pr, g);

        cub::DoubleBuffer<unsigned> dk(ka + (size_t)g * M, kb + (size_t)g * M);
        cub::DoubleBuffer<unsigned> dv(va + (size_t)g * M, vb + (size_t)g * M);
        size_t tb = TEMP_PER;
        cub::DeviceRadixSort::SortPairs(tmp + (size_t)g * TEMP_PER, tb,
                                        dk, dv, M, 0, 32, st);

        // Per-group decode overlaps other lanes' sorts; pass this group's
        // own current buffers (base pointers, kernel indexes by group).
        const unsigned* ksg = dk.Current() - (size_t)g * M;
        const unsigned* vsg = dv.Current() - (size_t)g * M;
        decode_kernel<<<dblocks, 256, 0, st>>>(ksg, vsg, pr, out, g);
    }

    // Join all side streams back into the capture stream.
    for (int s = 0; s < S; s++) {
        cudaEventRecord(ev_join[s], streams[s]);
        cudaStreamWaitEvent(0, ev_join[s], 0);
    }

    // Tear down capture-time objects (all side work joined into stream 0).
    for (int s = 0; s < S; s++) cudaStreamDestroy(streams[s]);
    cudaEventDestroy(ev_fork);
    for (int s = 0; s < S; s++) cudaEventDestroy(ev_join[s]);
}